// round 17
// baseline (speedup 1.0000x reference)
#include <cuda_runtime.h>
#include <cuda_fp16.h>
#include <cstdint>

// Problem constants
#define BATCH   524288
#define KDIM    128     // in_features (K)
#define NOUT    128     // out_features
#define TILE_M  32      // batch rows per CTA tile
#define NTILES  (BATCH / TILE_M)   // 16384
#define THREADS 128     // 4 warps; each warp = 32 rows x 32 outs
#define CTAS_PER_SM 4

// SMEM layout: fp32 cp.async stage (16KB) + two fp16 buffers (8KB each)
#define STAGE_BYTES (TILE_M * KDIM * 4)          // 16384
#define XBUF_BYTES  (TILE_M * KDIM * 2)          // 8192
#define XBUF_OFF    STAGE_BYTES                  // 16384
#define SMEM_TOTAL  (STAGE_BYTES + 2 * XBUF_BYTES)  // 32768 -> 4 CTAs/SM

// Swizzle for 256B fp16 rows: XOR row%8 (addr bits [8:10]) into 16B-chunk bits [4:6].
static __device__ __forceinline__ uint32_t sw(uint32_t a) {
    return a ^ ((a >> 4) & 0x70u);
}

static __device__ __forceinline__ uint32_t pack_h2(float a, float b) {
    __half2 h = __floats2half2_rn(a, b);
    return *reinterpret_cast<uint32_t*>(&h);
}

#define CP_ASYNC16(dst, src) \
    asm volatile("cp.async.cg.shared.global [%0], [%1], 16;" :: "r"(dst), "l"(src))
#define CP_COMMIT() asm volatile("cp.async.commit_group;")
#define CP_WAIT0()  asm volatile("cp.async.wait_group 0;" ::: "memory")

__global__ void __launch_bounds__(THREADS, CTAS_PER_SM) linear_hmma_kernel(
    const float* __restrict__ x, const float* __restrict__ w,
    const float* __restrict__ bias, float* __restrict__ out)
{
    extern __shared__ __align__(1024) char smem[];
    uint32_t sb = (uint32_t)__cvta_generic_to_shared(smem);

    const int tid   = threadIdx.x;
    const int lane  = tid & 31;
    const int warpN = tid >> 5;   // 0..3 : 32-out group (all warps share the 32 rows)
    const int g     = lane >> 2;  // groupID (0..7)
    const int tg    = lane & 3;   // thread-in-group (0..3)

    // ---- W fragments: fp32 -> fp16 once, pinned in registers for the whole run ----
    uint32_t wf[4][8][2];
#pragma unroll
    for (int nt = 0; nt < 4; ++nt) {
        const int n = warpN * 32 + nt * 8 + g;
        const float* wr = w + n * KDIM;
#pragma unroll
        for (int ks = 0; ks < 8; ++ks) {
            const int k0 = ks * 16 + tg * 2;
            wf[nt][ks][0] = pack_h2(__ldg(wr + k0),     __ldg(wr + k0 + 1));
            wf[nt][ks][1] = pack_h2(__ldg(wr + k0 + 8), __ldg(wr + k0 + 9));
        }
    }
    // bias for this thread's output columns
    float bs[4][2];
#pragma unroll
    for (int nt = 0; nt < 4; ++nt) {
        const int c = warpN * 32 + nt * 8 + tg * 2;
        bs[nt][0] = __ldg(bias + c);
        bs[nt][1] = __ldg(bias + c + 1);
    }

    // ldmatrix x4 lane addressing
    const uint32_t lrow  = (uint32_t)(lane & 15);
    const uint32_t lcolb = (lane & 16) ? 16u : 0u;

    // per-thread staging addresses (thread converts exactly the chunks it copied)
    const uint32_t stg_base = sb + (uint32_t)(tid * 16);   // float4 slot for i=0

    int tile = blockIdx.x;
    const int stride = gridDim.x;

    // ---- prologue: cp.async tile0 -> stage, wait, convert -> fp16 buf0 ----
    {
        const char* src = (const char*)(x + (size_t)tile * (TILE_M * KDIM)) + tid * 16;
#pragma unroll
        for (int i = 0; i < 8; ++i)
            CP_ASYNC16(stg_base + (uint32_t)(i * THREADS * 16), src + i * THREADS * 16);
        CP_COMMIT();
        CP_WAIT0();
#pragma unroll
        for (int i = 0; i < 8; ++i) {
            const int lin = i * THREADS + tid;
            const float4 v = *reinterpret_cast<const float4*>(smem + lin * 16);
            const uint32_t row = (uint32_t)(lin >> 5);
            const uint32_t k   = (uint32_t)((lin & 31) << 2);
            *reinterpret_cast<uint2*>(smem + XBUF_OFF + sw(row * 256u + k * 2u)) =
                make_uint2(pack_h2(v.x, v.y), pack_h2(v.z, v.w));
        }
    }
    __syncthreads();

    int db = 0;
    while (tile < NTILES) {
        const int nxt = tile + stride;
        const bool more = nxt < NTILES;

        // 1) cp.async the next tile into the fp32 stage (no registers held)
        if (more) {
            const char* src = (const char*)(x + (size_t)nxt * (TILE_M * KDIM)) + tid * 16;
#pragma unroll
            for (int i = 0; i < 8; ++i)
                CP_ASYNC16(stg_base + (uint32_t)(i * THREADS * 16), src + i * THREADS * 16);
            CP_COMMIT();
        }

        // 2) compute current tile: 8 k-steps x (2 ldmatrix.x4 + 8 mma)
        float acc[2][4][4];
#pragma unroll
        for (int mt = 0; mt < 2; ++mt)
#pragma unroll
            for (int nt = 0; nt < 4; ++nt)
#pragma unroll
                for (int j = 0; j < 4; ++j) acc[mt][nt][j] = 0.0f;

        const uint32_t bufbase = sb + (uint32_t)XBUF_OFF + (uint32_t)db * XBUF_BYTES;
#pragma unroll
        for (int ks = 0; ks < 8; ++ks) {
            uint32_t a[2][4];
#pragma unroll
            for (int mt = 0; mt < 2; ++mt) {
                const uint32_t addr =
                    bufbase + sw((lrow + (uint32_t)mt * 16u) * 256u + (uint32_t)ks * 32u + lcolb);
                asm volatile(
                    "ldmatrix.sync.aligned.m8n8.x4.shared.b16 {%0,%1,%2,%3}, [%4];"
                    : "=r"(a[mt][0]), "=r"(a[mt][1]), "=r"(a[mt][2]), "=r"(a[mt][3])
                    : "r"(addr));
            }
#pragma unroll
            for (int mt = 0; mt < 2; ++mt)
#pragma unroll
                for (int nt = 0; nt < 4; ++nt)
                    asm volatile(
                        "mma.sync.aligned.m16n8k16.row.col.f32.f16.f16.f32 "
                        "{%0,%1,%2,%3}, {%4,%5,%6,%7}, {%8,%9}, {%0,%1,%2,%3};"
                        : "+f"(acc[mt][nt][0]), "+f"(acc[mt][nt][1]),
                          "+f"(acc[mt][nt][2]), "+f"(acc[mt][nt][3])
                        : "r"(a[mt][0]), "r"(a[mt][1]), "r"(a[mt][2]), "r"(a[mt][3]),
                          "r"(wf[nt][ks][0]), "r"(wf[nt][ks][1]));
        }

        // 3) epilogue: bias add + streaming stores (writes flow while cp.async lands)
        float* ob = out + (size_t)tile * (TILE_M * NOUT);
#pragma unroll
        for (int mt = 0; mt < 2; ++mt) {
            const int r0 = mt * 16 + g;
#pragma unroll
            for (int nt = 0; nt < 4; ++nt) {
                const int c = warpN * 32 + nt * 8 + tg * 2;
                float2 v0 = make_float2(acc[mt][nt][0] + bs[nt][0], acc[mt][nt][1] + bs[nt][1]);
                float2 v1 = make_float2(acc[mt][nt][2] + bs[nt][0], acc[mt][nt][3] + bs[nt][1]);
                __stcs(reinterpret_cast<float2*>(ob + (size_t)r0 * NOUT + c), v0);
                __stcs(reinterpret_cast<float2*>(ob + (size_t)(r0 + 8) * NOUT + c), v1);
            }
        }

        // 4) wait for staged tile, convert own chunks into the other fp16 buffer
        //    (no barrier needed: each thread reads only the chunks it cp.async'd)
        if (more) {
            CP_WAIT0();
            char* xb = smem + XBUF_OFF + (db ^ 1) * XBUF_BYTES;
#pragma unroll
            for (int i = 0; i < 8; ++i) {
                const int lin = i * THREADS + tid;
                const float4 v = *reinterpret_cast<const float4*>(smem + lin * 16);
                const uint32_t row = (uint32_t)(lin >> 5);
                const uint32_t k   = (uint32_t)((lin & 31) << 2);
                *reinterpret_cast<uint2*>(xb + sw(row * 256u + k * 2u)) =
                    make_uint2(pack_h2(v.x, v.y), pack_h2(v.z, v.w));
            }
        }

        __syncthreads();   // fp16 buffer handoff + stage reuse barrier
        tile = nxt;
        db ^= 1;
    }
}

extern "C" void kernel_launch(void* const* d_in, const int* in_sizes, int n_in,
                              void* d_out, int out_size) {
    const float* x  = (const float*)d_in[0];   // enc_x  [524288, 128]
    const float* w  = (const float*)d_in[1];   // weight [128, 128]
    const float* b  = (const float*)d_in[2];   // bias   [128]
    float* out = (float*)d_out;                // [524288, 128] fp32

    int dev = 0;
    cudaGetDevice(&dev);
    int sms = 148;
    cudaDeviceGetAttribute(&sms, cudaDevAttrMultiProcessorCount, dev);

    cudaFuncSetAttribute(linear_hmma_kernel,
                         cudaFuncAttributeMaxDynamicSharedMemorySize, SMEM_TOTAL);

    // 4 CTAs per SM (16 warps): latency hiding via occupancy, cp.async removes
    // the register prefetch that previously capped residency at 3 CTAs
    linear_hmma_kernel<<<sms * CTAS_PER_SM, THREADS, SMEM_TOTAL>>>(x, w, b, out);
}